// round 1
// baseline (speedup 1.0000x reference)
#include <cuda_runtime.h>
#include <math.h>

#define NB   16384   // batch rows
#define DD   768     // D
#define KK   4       // K directions
#define NH1  512
#define NH2  256

// Scratch (alloc-free rule: __device__ globals)
__device__ float g_h1[(size_t)NB * NH1];
__device__ float g_h2[(size_t)NB * NH2];

// ---------------- block reductions (256 threads, 8 warps) ----------------

__device__ __forceinline__ float block_reduce_sum(float v, float* red, int tid) {
    const int lane = tid & 31, wid = tid >> 5;
    #pragma unroll
    for (int o = 16; o > 0; o >>= 1) v += __shfl_xor_sync(0xffffffffu, v, o);
    __syncthreads();                 // protect red from previous use
    if (lane == 0) red[wid] = v;
    __syncthreads();
    float r = 0.0f;
    #pragma unroll
    for (int i = 0; i < 8; i++) r += red[i];
    return r;
}

__device__ __forceinline__ float block_reduce_max(float v, float* red, int tid) {
    const int lane = tid & 31, wid = tid >> 5;
    #pragma unroll
    for (int o = 16; o > 0; o >>= 1) v = fmaxf(v, __shfl_xor_sync(0xffffffffu, v, o));
    __syncthreads();
    if (lane == 0) red[wid] = v;
    __syncthreads();
    float r = -3.402823466e+38f;
    #pragma unroll
    for (int i = 0; i < 8; i++) r = fmaxf(r, red[i]);
    return r;
}

// ---------------- tiled SGEMM + bias: C[M,N] = A[M,K] @ W[K,N] + b ----------------
// Requirements (all satisfied by our shapes): M%BM==0, N%BN==0, K%BK==0,
// K%4==0, N%4==0.

template <int BM, int BN, int BK, int TM, int TN>
__global__ __launch_bounds__((BM / TM) * (BN / TN))
void sgemm_bias(int M, int N, int K,
                const float* __restrict__ A,
                const float* __restrict__ W,
                const float* __restrict__ bias,
                float* __restrict__ C)
{
    constexpr int NT = (BM / TM) * (BN / TN);   // 256
    __shared__ __align__(16) float As[BM][BK];
    __shared__ __align__(16) float Ws[BK][BN];

    const int tid  = threadIdx.x;
    const int brow = blockIdx.y * BM;
    const int bcol = blockIdx.x * BN;
    const int trow = (tid / (BN / TN)) * TM;
    const int tcol = (tid % (BN / TN)) * TN;

    // A tile: BM*BK floats, float4 per thread per pass
    const int a_row = tid / (BK / 4);
    const int a_col = (tid % (BK / 4)) * 4;
    constexpr int A_ROWS_PER_PASS = (NT * 4) / BK;   // 64
    // W tile: BK*BN floats, 1 float4 per thread
    const int w_row = tid / (BN / 4);
    const int w_col = (tid % (BN / 4)) * 4;

    float acc[TM][TN] = {};

    for (int k0 = 0; k0 < K; k0 += BK) {
        #pragma unroll
        for (int r = 0; r < BM; r += A_ROWS_PER_PASS) {
            float4 av = *(const float4*)&A[(size_t)(brow + a_row + r) * K + k0 + a_col];
            *(float4*)&As[a_row + r][a_col] = av;
        }
        {
            float4 wv = *(const float4*)&W[(size_t)(k0 + w_row) * N + bcol + w_col];
            *(float4*)&Ws[w_row][w_col] = wv;
        }
        __syncthreads();

        #pragma unroll
        for (int k = 0; k < BK; k++) {
            float ar[TM];
            #pragma unroll
            for (int i = 0; i < TM; i++) ar[i] = As[trow + i][k];   // broadcast LDS
            float4 wv = *(const float4*)&Ws[k][tcol];
            float wr[TN] = {wv.x, wv.y, wv.z, wv.w};
            #pragma unroll
            for (int i = 0; i < TM; i++)
                #pragma unroll
                for (int j = 0; j < TN; j++)
                    acc[i][j] = fmaf(ar[i], wr[j], acc[i][j]);
        }
        __syncthreads();
    }

    #pragma unroll
    for (int i = 0; i < TM; i++) {
        float4 o;
        o.x = acc[i][0] + bias[bcol + tcol + 0];
        o.y = acc[i][1] + bias[bcol + tcol + 1];
        o.z = acc[i][2] + bias[bcol + tcol + 2];
        o.w = acc[i][3] + bias[bcol + tcol + 3];
        *(float4*)&C[(size_t)(brow + trow + i) * N + bcol + tcol] = o;
    }
}

// ---------------- LayerNorm + ReLU (in place), one block per row ----------------

template <int N>
__global__ __launch_bounds__(256)
void ln_relu_kernel(float* __restrict__ X,
                    const float* __restrict__ g,
                    const float* __restrict__ be)
{
    __shared__ float red[8];
    const int row = blockIdx.x;
    const int tid = threadIdx.x;
    float* x = X + (size_t)row * N;
    constexpr int PT = N / 256;

    float v[PT];
    float s = 0.0f;
    #pragma unroll
    for (int c = 0; c < PT; c++) { v[c] = x[tid + c * 256]; s += v[c]; }
    s = block_reduce_sum(s, red, tid);
    const float mu = s * (1.0f / N);

    float s2 = 0.0f;
    #pragma unroll
    for (int c = 0; c < PT; c++) { float d = v[c] - mu; s2 += d * d; }
    s2 = block_reduce_sum(s2, red, tid);
    const float inv = rsqrtf(s2 * (1.0f / N) + 1e-5f);

    #pragma unroll
    for (int c = 0; c < PT; c++) {
        const int i = tid + c * 256;
        x[i] = fmaxf((v[c] - mu) * inv * g[i] + be[i], 0.0f);
    }
}

// ---------------- finalize: softmax + attn-scale + Gram-Schmidt (in place) -----
// Wbuf holds W_flat [NB, KK*DD] on entry, W_ortho on exit.
// Abuf holds logits [NB, DD] on entry, attn on exit.
// 768 = 3 * 256: index i is owned exclusively by thread i%256 -> all per-element
// state lives in registers; only reductions need block cooperation.

__global__ __launch_bounds__(256)
void finalize_kernel(float* __restrict__ Wbuf, float* __restrict__ Abuf)
{
    __shared__ float red[8];
    const int row = blockIdx.x;
    const int tid = threadIdx.x;
    float* lg = Abuf + (size_t)row * DD;
    float* wp = Wbuf + (size_t)row * (KK * DD);

    // softmax over 768 logits
    float l[3];
    #pragma unroll
    for (int c = 0; c < 3; c++) l[c] = lg[tid + c * 256];
    float m = fmaxf(fmaxf(l[0], l[1]), l[2]);
    m = block_reduce_max(m, red, tid);

    float a[3];
    float s = 0.0f;
    #pragma unroll
    for (int c = 0; c < 3; c++) { a[c] = expf(l[c] - m); s += a[c]; }
    s = block_reduce_sum(s, red, tid);
    const float sinv = 1.0f / s;
    #pragma unroll
    for (int c = 0; c < 3; c++) { a[c] *= sinv; lg[tid + c * 256] = a[c]; }

    // W = W_flat * attn (broadcast over K)
    float w[KK][3];
    #pragma unroll
    for (int k = 0; k < KK; k++)
        #pragma unroll
        for (int c = 0; c < 3; c++)
            w[k][c] = wp[k * DD + tid + c * 256] * a[c];

    // sequential Gram-Schmidt, matching reference order exactly
    #pragma unroll
    for (int k = 0; k < KK; k++) {
        #pragma unroll
        for (int j = 0; j < KK; j++) {
            if (j < k) {   // uniform predicate -> block reduce is safe
                float p = 0.0f;
                #pragma unroll
                for (int c = 0; c < 3; c++) p += w[k][c] * w[j][c];
                p = block_reduce_sum(p, red, tid);
                #pragma unroll
                for (int c = 0; c < 3; c++) w[k][c] -= p * w[j][c];
            }
        }
        float n2 = 0.0f;
        #pragma unroll
        for (int c = 0; c < 3; c++) n2 += w[k][c] * w[k][c];
        n2 = block_reduce_sum(n2, red, tid);
        const float innorm = 1.0f / fmaxf(sqrtf(n2), 1e-12f);
        #pragma unroll
        for (int c = 0; c < 3; c++) {
            w[k][c] *= innorm;
            wp[k * DD + tid + c * 256] = w[k][c];
        }
    }
}

// ---------------- launch ----------------

extern "C" void kernel_launch(void* const* d_in, const int* in_sizes, int n_in,
                              void* d_out, int out_size)
{
    const float* emb = (const float*)d_in[0];
    const float* W1  = (const float*)d_in[1];
    const float* b1  = (const float*)d_in[2];
    const float* g1  = (const float*)d_in[3];
    const float* be1 = (const float*)d_in[4];
    const float* W2  = (const float*)d_in[5];
    const float* b2  = (const float*)d_in[6];
    const float* g2  = (const float*)d_in[7];
    const float* be2 = (const float*)d_in[8];
    const float* Wd  = (const float*)d_in[9];
    const float* bd  = (const float*)d_in[10];
    const float* Wa  = (const float*)d_in[11];
    const float* ba  = (const float*)d_in[12];

    float* out  = (float*)d_out;
    float* outW = out;                                   // [NB, KK, DD]
    float* outA = out + (size_t)NB * KK * DD;            // [NB, DD]

    float *h1 = nullptr, *h2 = nullptr;
    cudaGetSymbolAddress((void**)&h1, g_h1);
    cudaGetSymbolAddress((void**)&h2, g_h2);

    const dim3 blk(256);

    // h1 = relu(LN(emb @ W1 + b1))
    sgemm_bias<128, 64, 16, 8, 4>
        <<<dim3(NH1 / 64, NB / 128), blk>>>(NB, NH1, DD, emb, W1, b1, h1);
    ln_relu_kernel<NH1><<<NB, 256>>>(h1, g1, be1);

    // h2 = relu(LN(h1 @ W2 + b2))
    sgemm_bias<128, 64, 16, 8, 4>
        <<<dim3(NH2 / 64, NB / 128), blk>>>(NB, NH2, NH1, h1, W2, b2, h2);
    ln_relu_kernel<NH2><<<NB, 256>>>(h2, g2, be2);

    // W_flat = h2 @ Wd + bd  -> directly into output region
    sgemm_bias<128, 64, 16, 8, 4>
        <<<dim3((KK * DD) / 64, NB / 128), blk>>>(NB, KK * DD, NH2, h2, Wd, bd, outW);

    // logits = h2 @ Wa + ba  -> directly into output region
    sgemm_bias<128, 64, 16, 8, 4>
        <<<dim3(DD / 64, NB / 128), blk>>>(NB, DD, NH2, h2, Wa, ba, outA);

    // softmax + scale + Gram-Schmidt, in place
    finalize_kernel<<<NB, 256>>>(outW, outA);
}

// round 5
// speedup vs baseline: 1.6573x; 1.6573x over previous
#include <cuda_runtime.h>
#include <cuda_bf16.h>
#include <math.h>
#include <stdint.h>

#define NB   16384   // batch rows
#define DD   768     // D
#define KK   4       // K directions
#define NH1  512
#define NH2  256

// Scratch (alloc-free rule: __device__ globals)
__device__ float g_h1[(size_t)NB * NH1];
__device__ float g_h2[(size_t)NB * NH2];

// ======================= GEMM config =======================
#define BM 128
#define BN 64
#define BKC 32
#define GT 256                    // threads per CTA

#define AS_BYTES 16384            // 128 rows * 128B (hi|lo halves per row)
#define BS_BYTES 8192             // 2 split tiles * (32 rows * 128B)
#define MM_SMEM (2 * AS_BYTES + 2 * BS_BYTES)   // 49152 == default 48KB limit

__device__ __forceinline__ uint32_t smem_u32(const void* p) {
    uint32_t a;
    asm("{ .reg .u64 t; cvta.to.shared.u64 t, %1; cvt.u32.u64 %0, t; }"
        : "=r"(a) : "l"(p));
    return a;
}

__device__ __forceinline__ uint32_t sw128(uint32_t off) {   // bits[6:4] ^= bits[9:7]
    return off ^ ((off >> 3) & 0x70);
}

__device__ __forceinline__ void ldsm4(uint32_t& r0, uint32_t& r1, uint32_t& r2,
                                      uint32_t& r3, uint32_t addr) {
    asm volatile("ldmatrix.sync.aligned.m8n8.x4.shared.b16 {%0,%1,%2,%3}, [%4];"
                 : "=r"(r0), "=r"(r1), "=r"(r2), "=r"(r3) : "r"(addr));
}

__device__ __forceinline__ void ldsm4t(uint32_t& r0, uint32_t& r1, uint32_t& r2,
                                       uint32_t& r3, uint32_t addr) {
    asm volatile("ldmatrix.sync.aligned.m8n8.x4.trans.shared.b16 {%0,%1,%2,%3}, [%4];"
                 : "=r"(r0), "=r"(r1), "=r"(r2), "=r"(r3) : "r"(addr));
}

__device__ __forceinline__ void mma16816(float* d, const uint32_t* a, const uint32_t* b) {
    asm volatile(
        "mma.sync.aligned.m16n8k16.row.col.f32.bf16.bf16.f32 "
        "{%0,%1,%2,%3}, {%4,%5,%6,%7}, {%8,%9}, {%0,%1,%2,%3};"
        : "+f"(d[0]), "+f"(d[1]), "+f"(d[2]), "+f"(d[3])
        : "r"(a[0]), "r"(a[1]), "r"(a[2]), "r"(a[3]), "r"(b[0]), "r"(b[1]));
}

__device__ __forceinline__ uint32_t pack_bf2(__nv_bfloat16 x, __nv_bfloat16 y) {
    __nv_bfloat162 t = __halves2bfloat162(x, y);   // .x = low half
    return *reinterpret_cast<uint32_t*>(&t);
}

// split float pair -> (hi pair, lo pair) packed bf16x2
__device__ __forceinline__ void split2(float x, float y, uint32_t& hu, uint32_t& lu) {
    __nv_bfloat16 hx = __float2bfloat16_rn(x);
    __nv_bfloat16 hy = __float2bfloat16_rn(y);
    float lx = x - __bfloat162float(hx);
    float ly = y - __bfloat162float(hy);
    hu = pack_bf2(hx, hy);
    lu = pack_bf2(__float2bfloat16_rn(lx), __float2bfloat16_rn(ly));
}

// ---- global load of one BK chunk into registers ----
__device__ __forceinline__ void ldg_chunk(const float* __restrict__ A,
                                          const float* __restrict__ W,
                                          int N, int K, int brow, int bcol, int k0,
                                          int tid, float4* av, float4* wv) {
    const int r  = tid >> 1, kh = (tid & 1) * 16;
    const float* ap = A + (size_t)(brow + r) * K + k0 + kh;
    av[0] = *(const float4*)(ap + 0);
    av[1] = *(const float4*)(ap + 4);
    av[2] = *(const float4*)(ap + 8);
    av[3] = *(const float4*)(ap + 12);
    const int kb = tid >> 3, n0 = (tid & 7) * 8;
    const float* wp = W + (size_t)(k0 + kb) * N + bcol + n0;
    wv[0] = *(const float4*)(wp + 0);
    wv[1] = *(const float4*)(wp + 4);
}

// ---- convert + store chunk to smem (swizzled bf16 hi/lo) ----
__device__ __forceinline__ void sts_chunk(char* sm, int buf, int tid,
                                          const float4* av, const float4* wv) {
    char* As = sm + buf * AS_BYTES;
    char* Bs = sm + 2 * AS_BYTES + buf * BS_BYTES;
    const int r = tid >> 1, kh = (tid & 1) * 16;
    #pragma unroll
    for (int j = 0; j < 4; j++) {
        float4 v = av[j];
        uint32_t h0, l0, h1, l1;
        split2(v.x, v.y, h0, l0);
        split2(v.z, v.w, h1, l1);
        uint32_t off = (uint32_t)(r * 128 + (kh + 4 * j) * 2);
        *(uint2*)(As + sw128(off))      = make_uint2(h0, h1);
        *(uint2*)(As + sw128(off + 64)) = make_uint2(l0, l1);
    }
    const int kb = tid >> 3, n0 = (tid & 7) * 8;
    #pragma unroll
    for (int j = 0; j < 2; j++) {
        float4 v = wv[j];
        uint32_t h0, l0, h1, l1;
        split2(v.x, v.y, h0, l0);
        split2(v.z, v.w, h1, l1);
        uint32_t off = (uint32_t)(kb * 128 + (n0 + 4 * j) * 2);
        *(uint2*)(Bs + sw128(off))        = make_uint2(h0, h1);
        *(uint2*)(Bs + 4096 + sw128(off)) = make_uint2(l0, l1);
    }
}

// ======================= bf16x3 mma.sync GEMM =======================
// C[M,N] = A[M,K] @ W[K,N] + bias, fp32 in/out, ~fp32 accuracy.
// Requires: M%128==0, N%64==0, K%32==0.

__global__ __launch_bounds__(GT)
void mm_bf16x3(int M, int N, int K,
               const float* __restrict__ A,
               const float* __restrict__ W,
               const float* __restrict__ bias,
               float* __restrict__ C)
{
    extern __shared__ char sm[];
    const uint32_t sb = smem_u32(sm);
    const int tid  = threadIdx.x;
    const int lane = tid & 31;
    const int wid  = tid >> 5;
    const int wm   = (wid & 3) * 32;     // warp m offset (4 warps down)
    const int wn   = (wid >> 2) * 32;    // warp n offset (2 warps across)
    const int brow = blockIdx.y * BM;
    const int bcol = blockIdx.x * BN;

    float acc[2][4][4];
    #pragma unroll
    for (int i = 0; i < 2; i++)
        #pragma unroll
        for (int j = 0; j < 4; j++)
            #pragma unroll
            for (int q = 0; q < 4; q++) acc[i][j][q] = 0.0f;

    const int nch = K / BKC;
    float4 av[4], wv[2];

    // prologue: stage chunk 0
    ldg_chunk(A, W, N, K, brow, bcol, 0, tid, av, wv);
    sts_chunk(sm, 0, tid, av, wv);
    __syncthreads();

    for (int c = 0; c < nch; ++c) {
        if (c + 1 < nch)
            ldg_chunk(A, W, N, K, brow, bcol, (c + 1) * BKC, tid, av, wv);

        const uint32_t aB = sb + (c & 1) * AS_BYTES;
        const uint32_t bB = sb + 2 * AS_BYTES + (c & 1) * BS_BYTES;

        #pragma unroll
        for (int kt = 0; kt < 2; kt++) {
            // A fragments: [split][mtile][4 regs]
            uint32_t Af[2][2][4];
            #pragma unroll
            for (int s = 0; s < 2; s++)
                #pragma unroll
                for (int mt = 0; mt < 2; mt++) {
                    int row = wm + mt * 16 + (lane & 15);
                    int c16 = s * 4 + kt * 2 + (lane >> 4);
                    ldsm4(Af[s][mt][0], Af[s][mt][1], Af[s][mt][2], Af[s][mt][3],
                          aB + sw128((uint32_t)(row * 128 + c16 * 16)));
                }
            // B fragments: [split][ntile8][2 regs] via x4.trans (2 ntiles per op)
            uint32_t Bf[2][4][2];
            #pragma unroll
            for (int s = 0; s < 2; s++)
                #pragma unroll
                for (int np = 0; np < 2; np++) {
                    int m   = lane >> 3;          // matrix index 0..3
                    int r8  = lane & 7;
                    int krow = kt * 16 + (m & 1) * 8 + r8;
                    int c16  = (wn >> 3) + np * 2 + (m >> 1);   // 8 n-elems = 1 unit
                    uint32_t addr = bB + s * 4096 +
                                    sw128((uint32_t)(krow * 128 + c16 * 16));
                    ldsm4t(Bf[s][np * 2][0], Bf[s][np * 2][1],
                           Bf[s][np * 2 + 1][0], Bf[s][np * 2 + 1][1], addr);
                }
            // 3-term split MMA
            #pragma unroll
            for (int mt = 0; mt < 2; mt++)
                #pragma unroll
                for (int nt = 0; nt < 4; nt++) {
                    mma16816(acc[mt][nt], Af[0][mt], Bf[0][nt]);   // hi*hi
                    mma16816(acc[mt][nt], Af[0][mt], Bf[1][nt]);   // hi*lo
                    mma16816(acc[mt][nt], Af[1][mt], Bf[0][nt]);   // lo*hi
                }
        }

        if (c + 1 < nch)
            sts_chunk(sm, (c + 1) & 1, tid, av, wv);
        __syncthreads();
    }

    // ---- epilogue: regs + bias -> gmem ----
    const int g = lane >> 2, tg = lane & 3;
    #pragma unroll
    for (int mt = 0; mt < 2; mt++)
        #pragma unroll
        for (int nt = 0; nt < 4; nt++) {
            const int col = bcol + wn + nt * 8 + 2 * tg;
            const float bx = __ldg(&bias[col]);
            const float by = __ldg(&bias[col + 1]);
            const int row = brow + wm + mt * 16 + g;
            float2 o0 = make_float2(acc[mt][nt][0] + bx, acc[mt][nt][1] + by);
            float2 o1 = make_float2(acc[mt][nt][2] + bx, acc[mt][nt][3] + by);
            *(float2*)&C[(size_t)row * N + col]       = o0;
            *(float2*)&C[(size_t)(row + 8) * N + col] = o1;
        }
}

// ======================= block reductions =======================

__device__ __forceinline__ float block_reduce_sum(float v, float* red, int tid) {
    const int lane = tid & 31, wd = tid >> 5;
    #pragma unroll
    for (int o = 16; o > 0; o >>= 1) v += __shfl_xor_sync(0xffffffffu, v, o);
    __syncthreads();
    if (lane == 0) red[wd] = v;
    __syncthreads();
    float r = 0.0f;
    #pragma unroll
    for (int i = 0; i < 8; i++) r += red[i];
    return r;
}

__device__ __forceinline__ float block_reduce_max(float v, float* red, int tid) {
    const int lane = tid & 31, wd = tid >> 5;
    #pragma unroll
    for (int o = 16; o > 0; o >>= 1) v = fmaxf(v, __shfl_xor_sync(0xffffffffu, v, o));
    __syncthreads();
    if (lane == 0) red[wd] = v;
    __syncthreads();
    float r = -3.402823466e+38f;
    #pragma unroll
    for (int i = 0; i < 8; i++) r = fmaxf(r, red[i]);
    return r;
}

// ======================= LayerNorm + ReLU (in place) =======================

template <int N>
__global__ __launch_bounds__(256)
void ln_relu_kernel(float* __restrict__ X,
                    const float* __restrict__ g,
                    const float* __restrict__ be)
{
    __shared__ float red[8];
    const int row = blockIdx.x;
    const int tid = threadIdx.x;
    float* x = X + (size_t)row * N;
    constexpr int PT = N / 256;

    float v[PT];
    float s = 0.0f;
    #pragma unroll
    for (int c = 0; c < PT; c++) { v[c] = x[tid + c * 256]; s += v[c]; }
    s = block_reduce_sum(s, red, tid);
    const float mu = s * (1.0f / N);

    float s2 = 0.0f;
    #pragma unroll
    for (int c = 0; c < PT; c++) { float d = v[c] - mu; s2 += d * d; }
    s2 = block_reduce_sum(s2, red, tid);
    const float inv = rsqrtf(s2 * (1.0f / N) + 1e-5f);

    #pragma unroll
    for (int c = 0; c < PT; c++) {
        const int i = tid + c * 256;
        x[i] = fmaxf((v[c] - mu) * inv * g[i] + be[i], 0.0f);
    }
}

// ======================= finalize: softmax + scale + Gram-Schmidt =======================

__global__ __launch_bounds__(256)
void finalize_kernel(float* __restrict__ Wbuf, float* __restrict__ Abuf)
{
    __shared__ float red[8];
    const int row = blockIdx.x;
    const int tid = threadIdx.x;
    float* lg = Abuf + (size_t)row * DD;
    float* wp = Wbuf + (size_t)row * (KK * DD);

    float l[3];
    #pragma unroll
    for (int c = 0; c < 3; c++) l[c] = lg[tid + c * 256];
    float m = fmaxf(fmaxf(l[0], l[1]), l[2]);
    m = block_reduce_max(m, red, tid);

    float a[3];
    float s = 0.0f;
    #pragma unroll
    for (int c = 0; c < 3; c++) { a[c] = expf(l[c] - m); s += a[c]; }
    s = block_reduce_sum(s, red, tid);
    const float sinv = 1.0f / s;
    #pragma unroll
    for (int c = 0; c < 3; c++) { a[c] *= sinv; lg[tid + c * 256] = a[c]; }

    float w[KK][3];
    #pragma unroll
    for (int k = 0; k < KK; k++)
        #pragma unroll
        for (int c = 0; c < 3; c++)
            w[k][c] = wp[k * DD + tid + c * 256] * a[c];

    #pragma unroll
    for (int k = 0; k < KK; k++) {
        #pragma unroll
        for (int j = 0; j < KK; j++) {
            if (j < k) {
                float p = 0.0f;
                #pragma unroll
                for (int c = 0; c < 3; c++) p += w[k][c] * w[j][c];
                p = block_reduce_sum(p, red, tid);
                #pragma unroll
                for (int c = 0; c < 3; c++) w[k][c] -= p * w[j][c];
            }
        }
        float n2 = 0.0f;
        #pragma unroll
        for (int c = 0; c < 3; c++) n2 += w[k][c] * w[k][c];
        n2 = block_reduce_sum(n2, red, tid);
        const float innorm = 1.0f / fmaxf(sqrtf(n2), 1e-12f);
        #pragma unroll
        for (int c = 0; c < 3; c++) {
            w[k][c] *= innorm;
            wp[k * DD + tid + c * 256] = w[k][c];
        }
    }
}

// ======================= launch =======================

extern "C" void kernel_launch(void* const* d_in, const int* in_sizes, int n_in,
                              void* d_out, int out_size)
{
    const float* emb = (const float*)d_in[0];
    const float* W1  = (const float*)d_in[1];
    const float* b1  = (const float*)d_in[2];
    const float* g1  = (const float*)d_in[3];
    const float* be1 = (const float*)d_in[4];
    const float* W2  = (const float*)d_in[5];
    const float* b2  = (const float*)d_in[6];
    const float* g2  = (const float*)d_in[7];
    const float* be2 = (const float*)d_in[8];
    const float* Wd  = (const float*)d_in[9];
    const float* bd  = (const float*)d_in[10];
    const float* Wa  = (const float*)d_in[11];
    const float* ba  = (const float*)d_in[12];

    float* out  = (float*)d_out;
    float* outW = out;                                   // [NB, KK, DD]
    float* outA = out + (size_t)NB * KK * DD;            // [NB, DD]

    float *h1 = nullptr, *h2 = nullptr;
    cudaGetSymbolAddress((void**)&h1, g_h1);
    cudaGetSymbolAddress((void**)&h2, g_h2);

    // h1 = relu(LN(emb @ W1 + b1))
    mm_bf16x3<<<dim3(NH1 / BN, NB / BM), GT, MM_SMEM>>>(NB, NH1, DD, emb, W1, b1, h1);
    ln_relu_kernel<NH1><<<NB, 256>>>(h1, g1, be1);

    // h2 = relu(LN(h1 @ W2 + b2))
    mm_bf16x3<<<dim3(NH2 / BN, NB / BM), GT, MM_SMEM>>>(NB, NH2, NH1, h1, W2, b2, h2);
    ln_relu_kernel<NH2><<<NB, 256>>>(h2, g2, be2);

    // W_flat = h2 @ Wd + bd  -> output region
    mm_bf16x3<<<dim3((KK * DD) / BN, NB / BM), GT, MM_SMEM>>>(NB, KK * DD, NH2, h2, Wd, bd, outW);

    // logits = h2 @ Wa + ba  -> output region
    mm_bf16x3<<<dim3(DD / BN, NB / BM), GT, MM_SMEM>>>(NB, DD, NH2, h2, Wa, ba, outA);

    // softmax + scale + Gram-Schmidt, in place
    finalize_kernel<<<NB, 256>>>(outW, outA);
}